// round 2
// baseline (speedup 1.0000x reference)
#include <cuda_runtime.h>
#include <cuda_fp16.h>
#include <cstdint>
#include <cstddef>

// ============================================================
// Problem constants
// ============================================================
constexpr int N_ACT = 200000;
constexpr int CDIM  = 128;
constexpr int KOFF  = 27;
constexpr float BN_EPS = 1e-4f;

// Conv tiling
constexpr int BM           = 256;                       // rows per CTA
constexpr int NBLK         = (N_ACT + BM - 1) / BM;     // 782
constexpr int CONV_THREADS = 512;                       // 16 warps: 4(M) x 4(N)

// SMEM: padded rows (272B) make ldmatrix conflict-free (272 mod 128 = 16)
constexpr uint32_t ROWB   = 272;
constexpr uint32_t A_BUF  = 256u * ROWB;                // 69632
constexpr uint32_t B_BUF  = 128u * ROWB;                // 34816
constexpr uint32_t STAGE  = A_BUF + B_BUF;              // 104448
constexpr uint32_t SMEM_TOTAL = 2u * STAGE;             // 208896 (~204KB)

// ============================================================
// Device scratch
// ============================================================
__device__ __align__(16) __half g_Af16[(size_t)N_ACT * CDIM];          // 51.2 MB
__device__ __align__(16) __half g_Wt16[(size_t)KOFF * CDIM * CDIM];    // [k][cout][cin]
__device__ float g_psum[NBLK * CDIM];
__device__ float g_psq [NBLK * CDIM];
__device__ __align__(16) float g_scale[CDIM];
__device__ __align__(16) float g_bias [CDIM];

// ============================================================
// Helpers
// ============================================================
__device__ __forceinline__ uint32_t smem_u32(const void* p) {
    uint32_t a;
    asm("{ .reg .u64 t; cvta.to.shared.u64 t, %1; cvt.u32.u64 %0, t; }" : "=r"(a) : "l"(p));
    return a;
}

__device__ __forceinline__ void cp_async16(uint32_t dst, const void* src) {
    asm volatile("cp.async.cg.shared.global [%0], [%1], 16;" :: "r"(dst), "l"(src) : "memory");
}
__device__ __forceinline__ void sts_zero16(uint32_t dst) {
    asm volatile("st.shared.v4.b32 [%0], {%1, %1, %1, %1};" :: "r"(dst), "r"(0u) : "memory");
}
__device__ __forceinline__ void cp_commit() {
    asm volatile("cp.async.commit_group;" ::: "memory");
}
template <int N>
__device__ __forceinline__ void cp_wait() {
    asm volatile("cp.async.wait_group %0;" :: "n"(N) : "memory");
}

__device__ __forceinline__ void ldsm_x4(uint32_t* r, uint32_t addr) {
    asm volatile("ldmatrix.sync.aligned.m8n8.x4.shared.b16 {%0,%1,%2,%3}, [%4];"
                 : "=r"(r[0]), "=r"(r[1]), "=r"(r[2]), "=r"(r[3]) : "r"(addr));
}

__device__ __forceinline__ void mma16816(float* d, const uint32_t* a, const uint32_t* b) {
    asm volatile(
        "mma.sync.aligned.m16n8k16.row.col.f32.f16.f16.f32 "
        "{%0,%1,%2,%3}, {%4,%5,%6,%7}, {%8,%9}, {%0,%1,%2,%3};"
        : "+f"(d[0]), "+f"(d[1]), "+f"(d[2]), "+f"(d[3])
        : "r"(a[0]), "r"(a[1]), "r"(a[2]), "r"(a[3]), "r"(b[0]), "r"(b[1]));
}

// ============================================================
// Kernel 1a: features fp32 -> fp16
// ============================================================
__global__ void cvt_features_kernel(const float* __restrict__ f) {
    size_t idx = (size_t)blockIdx.x * blockDim.x + threadIdx.x;   // float4 chunk
    if (idx >= (size_t)N_ACT * CDIM / 4) return;
    float4 v = reinterpret_cast<const float4*>(f)[idx];
    __half2* dst = reinterpret_cast<__half2*>(g_Af16) + 2 * idx;
    dst[0] = __floats2half2_rn(v.x, v.y);
    dst[1] = __floats2half2_rn(v.z, v.w);
}

// ============================================================
// Kernel 1b: W [k][cin][cout] fp32 -> Wt [k][cout][cin] fp16
// ============================================================
__global__ void cvt_w_kernel(const float* __restrict__ W) {
    int m = blockIdx.x * blockDim.x + threadIdx.x;   // 27*128*128 exact
    int k   = m >> 14;
    int rem = m & 16383;
    int c   = rem >> 7;   // cout
    int j   = rem & 127;  // cin
    g_Wt16[m] = __float2half_rn(W[(k << 14) + (j << 7) + c]);
}

// ============================================================
// Kernel 2: gathered sparse conv via mma.sync (HMMA fp16 -> fp32)
// ============================================================
__global__ void __launch_bounds__(CONV_THREADS, 1)
conv_kernel(const int* __restrict__ nbr, float* __restrict__ out) {
    extern __shared__ char smem[];
    const uint32_t sb = smem_u32(smem);
    const int tid = threadIdx.x;
    const int wid = tid >> 5;
    const int lid = tid & 31;
    const int wm  = wid & 3;    // M group (64 rows)
    const int wn  = wid >> 2;   // N group (32 cols)
    const int row0 = blockIdx.x * BM;

    float acc[4][4][4];
    #pragma unroll
    for (int a = 0; a < 4; a++)
        #pragma unroll
        for (int b = 0; b < 4; b++)
            #pragma unroll
            for (int c = 0; c < 4; c++) acc[a][b][c] = 0.f;

    // ---- stage loader: A gather (256 rows x 256B) + B = Wt[k] (128 x 256B) ----
    auto load_stage = [&](int k, int buf) {
        const uint32_t base = sb + (uint32_t)buf * STAGE;
        // A: thread -> (row = tid>>1, half = tid&1) : 8 x 16B contiguous
        {
            int r    = tid >> 1;
            int half = tid & 1;
            int i    = row0 + r;
            int idx  = (i < N_ACT) ? __ldg(&nbr[(size_t)k * N_ACT + i]) : -1;
            uint32_t dst = base + (uint32_t)r * ROWB + (uint32_t)half * 128u;
            if (idx >= 0) {
                const char* src = (const char*)g_Af16 + (size_t)idx * 256 + (size_t)half * 128;
                #pragma unroll
                for (int c = 0; c < 8; c++)
                    cp_async16(dst + c * 16u, src + c * 16);
            } else {
                #pragma unroll
                for (int c = 0; c < 8; c++)
                    sts_zero16(dst + c * 16u);
            }
        }
        // B: thread -> (n = tid>>2, quarter = tid&3) : 4 x 16B contiguous
        {
            int n = tid >> 2;
            int q = tid & 3;
            uint32_t dst = base + A_BUF + (uint32_t)n * ROWB + (uint32_t)q * 64u;
            const char* src = (const char*)g_Wt16 + ((size_t)k * 128 + n) * 256 + (size_t)q * 64;
            #pragma unroll
            for (int c = 0; c < 4; c++)
                cp_async16(dst + c * 16u, src + c * 16);
        }
        cp_commit();
    };

    // ---- compute one stage from buffer ----
    auto compute_stage = [&](int buf) {
        const uint32_t abase = sb + (uint32_t)buf * STAGE;
        const uint32_t bbase = abase + A_BUF;
        // per-lane static pieces of ldmatrix addresses
        const uint32_t a_row  = (uint32_t)(wm * 64 + (lid & 15));
        const uint32_t a_coff = (uint32_t)(lid >> 4) * 16u;
        const uint32_t b_row  = (uint32_t)(wn * 32 + (lid & 7) + ((lid & 16) ? 8 : 0));
        const uint32_t b_coff = (uint32_t)((lid >> 3) & 1) * 16u;
        #pragma unroll
        for (int ks = 0; ks < 8; ks++) {
            uint32_t af[4][4];
            #pragma unroll
            for (int mf = 0; mf < 4; mf++)
                ldsm_x4(af[mf], abase + (a_row + mf * 16u) * ROWB + (uint32_t)ks * 32u + a_coff);
            uint32_t bf[4][2];
            #pragma unroll
            for (int bh = 0; bh < 2; bh++) {
                uint32_t t[4];
                ldsm_x4(t, bbase + (b_row + bh * 16u) * ROWB + (uint32_t)ks * 32u + b_coff);
                bf[2 * bh + 0][0] = t[0]; bf[2 * bh + 0][1] = t[1];
                bf[2 * bh + 1][0] = t[2]; bf[2 * bh + 1][1] = t[3];
            }
            #pragma unroll
            for (int mf = 0; mf < 4; mf++)
                #pragma unroll
                for (int nf = 0; nf < 4; nf++)
                    mma16816(acc[mf][nf], af[mf], bf[nf]);
        }
    };

    // ---- pipelined loop over 27 offsets ----
    load_stage(0, 0);
    #pragma unroll 1
    for (int k = 0; k < KOFF; k++) {
        const int buf = k & 1;
        if (k + 1 < KOFF) {
            load_stage(k + 1, buf ^ 1);
            cp_wait<1>();
        } else {
            cp_wait<0>();
        }
        __syncthreads();
        compute_stage(buf);
        __syncthreads();
    }

    // ---- epilogue: store conv output (pre-BN) ----
    {
        const int rbase = row0 + wm * 64 + (lid >> 2);
        const int cbase = wn * 32 + (lid & 3) * 2;
        #pragma unroll
        for (int mf = 0; mf < 4; mf++) {
            #pragma unroll
            for (int h = 0; h < 2; h++) {        // row halves (+0 / +8)
                int r = rbase + mf * 16 + h * 8;
                if (r < N_ACT) {
                    float* dst = out + (size_t)r * CDIM + cbase;
                    #pragma unroll
                    for (int nf = 0; nf < 4; nf++) {
                        float2 v = make_float2(acc[mf][nf][2 * h], acc[mf][nf][2 * h + 1]);
                        *reinterpret_cast<float2*>(dst + nf * 8) = v;
                    }
                }
            }
        }
    }

    // ---- fused BN partials from registers (deterministic, no atomics) ----
    {
        float s[8], q[8];
        #pragma unroll
        for (int nf = 0; nf < 4; nf++)
            #pragma unroll
            for (int jj = 0; jj < 2; jj++) {
                float ss = 0.f, qq = 0.f;
                #pragma unroll
                for (int mf = 0; mf < 4; mf++) {
                    float v0 = acc[mf][nf][jj];        // row half 0
                    float v1 = acc[mf][nf][jj + 2];    // row half 1
                    ss += v0 + v1;
                    qq = fmaf(v0, v0, qq);
                    qq = fmaf(v1, v1, qq);
                }
                s[nf * 2 + jj] = ss;
                q[nf * 2 + jj] = qq;
            }
        // reduce across lanes sharing the same (lid&3): strides 4, 8, 16
        #pragma unroll
        for (int st = 4; st <= 16; st <<= 1)
            #pragma unroll
            for (int j = 0; j < 8; j++) {
                s[j] += __shfl_xor_sync(0xFFFFFFFFu, s[j], st);
                q[j] += __shfl_xor_sync(0xFFFFFFFFu, q[j], st);
            }
        __syncthreads();   // tiles no longer needed; reuse smem for reduction
        float* red = reinterpret_cast<float*>(smem);   // [2][4][128]
        if (lid < 4) {
            #pragma unroll
            for (int nf = 0; nf < 4; nf++)
                #pragma unroll
                for (int jj = 0; jj < 2; jj++) {
                    int ch = wn * 32 + nf * 8 + lid * 2 + jj;
                    red[wm * 128 + ch]       = s[nf * 2 + jj];
                    red[512 + wm * 128 + ch] = q[nf * 2 + jj];
                }
        }
        __syncthreads();
        if (tid < CDIM) {
            float ts = 0.f, tq = 0.f;
            #pragma unroll
            for (int w = 0; w < 4; w++) {
                ts += red[w * 128 + tid];
                tq += red[512 + w * 128 + tid];
            }
            g_psum[blockIdx.x * CDIM + tid] = ts;
            g_psq [blockIdx.x * CDIM + tid] = tq;
        }
    }
}

// ============================================================
// Kernel 3: finalize BN scale/bias (deterministic fixed-order reduce)
// ============================================================
__global__ void bn_final_kernel(const float* __restrict__ gamma, const float* __restrict__ beta) {
    int c = threadIdx.x;
    float s = 0.f, q = 0.f;
    for (int b = 0; b < NBLK; b++) {
        s += g_psum[b * CDIM + c];
        q += g_psq [b * CDIM + c];
    }
    float mean = s / (float)N_ACT;
    float var  = q / (float)N_ACT - mean * mean;
    float sc   = gamma[c] * rsqrtf(var + BN_EPS);
    g_scale[c] = sc;
    g_bias[c]  = beta[c] - mean * sc;
}

// ============================================================
// Kernel 4: apply BN + ReLU elementwise
// ============================================================
__global__ void bn_apply_kernel(float* __restrict__ out) {
    size_t idx = (size_t)blockIdx.x * blockDim.x + threadIdx.x;   // float4 chunk
    if (idx >= (size_t)N_ACT * CDIM / 4) return;
    int c4 = (int)(idx & 31);   // 32 float4 per row
    float4 v  = reinterpret_cast<float4*>(out)[idx];
    float4 sc = reinterpret_cast<float4*>(g_scale)[c4];
    float4 bi = reinterpret_cast<float4*>(g_bias)[c4];
    v.x = fmaxf(fmaf(v.x, sc.x, bi.x), 0.f);
    v.y = fmaxf(fmaf(v.y, sc.y, bi.y), 0.f);
    v.z = fmaxf(fmaf(v.z, sc.z, bi.z), 0.f);
    v.w = fmaxf(fmaf(v.w, sc.w, bi.w), 0.f);
    reinterpret_cast<float4*>(out)[idx] = v;
}

// ============================================================
// Launch
// ============================================================
extern "C" void kernel_launch(void* const* d_in, const int* in_sizes, int n_in,
                              void* d_out, int out_size) {
    const float* features = (const float*)d_in[0];
    const int*   nbr      = (const int*)d_in[1];
    const float* W        = (const float*)d_in[2];
    const float* gamma    = (const float*)d_in[3];
    const float* beta     = (const float*)d_in[4];
    float* out = (float*)d_out;

    cudaFuncSetAttribute((const void*)conv_kernel,
                         cudaFuncAttributeMaxDynamicSharedMemorySize, SMEM_TOTAL);

    const int chunks = N_ACT * CDIM / 4;          // 6,400,000
    cvt_features_kernel<<<(chunks + 255) / 256, 256>>>(features);
    cvt_w_kernel<<<KOFF * CDIM * CDIM / 256, 256>>>(W);
    conv_kernel<<<NBLK, CONV_THREADS, SMEM_TOTAL>>>(nbr, out);
    bn_final_kernel<<<1, CDIM>>>(gamma, beta);
    bn_apply_kernel<<<(chunks + 255) / 256, 256>>>(out);
}

// round 3
// speedup vs baseline: 1.2729x; 1.2729x over previous
#include <cuda_runtime.h>
#include <cuda_fp16.h>
#include <cstdint>
#include <cstddef>

// ============================================================
// Problem constants
// ============================================================
constexpr int N_ACT = 200000;
constexpr int CDIM  = 128;
constexpr int KOFF  = 27;
constexpr float BN_EPS = 1e-4f;

constexpr int BM           = 256;                       // output rows per CTA
constexpr int NBLK         = (N_ACT + BM - 1) / BM;     // 782
constexpr int CONV_THREADS = 512;                       // 16 warps

// SMEM layout (dynamic). ROWB=272 keeps ldmatrix conflict-free.
constexpr uint32_t ROWB     = 272;
constexpr uint32_t A_TILE   = 64u * ROWB;               // 17408 (compact 64-row tile)
constexpr uint32_t OFF_A    = 0;                        // 2 tiles
constexpr uint32_t OFF_B    = OFF_A + 2u * A_TILE;      // 34816 ; 2 x 128x272
constexpr uint32_t B_TILE   = 128u * ROWB;              // 34816
constexpr uint32_t OFF_STG  = OFF_B + 2u * B_TILE;      // 104448
constexpr uint32_t STG_STRIDE = 136;                    // floats
constexpr uint32_t OFF_CIDX = OFF_STG + 64u * STG_STRIDE * 4u;   // 139264 ; 27*256 int32
constexpr uint32_t OFF_POS  = OFF_CIDX + 27648;         // 166912 ; 27*256 int16
constexpr uint32_t OFF_CNT  = OFF_POS + 13824;          // 180736 ; 27 int (pad 128)
constexpr uint32_t OFF_WTOT = OFF_CNT + 128;            // 180864 ; 8 int
constexpr uint32_t OFF_WORK = OFF_WTOT + 32;            // 180896 ; 112 int
constexpr uint32_t OFF_NW   = OFF_WORK + 448;           // 181344
constexpr uint32_t SMEM_TOTAL = OFF_NW + 32;            // 181376

// ============================================================
// Device scratch
// ============================================================
__device__ __align__(16) __half g_Af16[(size_t)N_ACT * CDIM];          // 51.2 MB
__device__ __align__(16) __half g_Wt16[(size_t)KOFF * CDIM * CDIM];    // [k][cout][cin]
__device__ float g_psum[NBLK * CDIM];
__device__ float g_psq [NBLK * CDIM];
__device__ __align__(16) float g_scale[CDIM];
__device__ __align__(16) float g_bias [CDIM];

// ============================================================
// Helpers
// ============================================================
__device__ __forceinline__ uint32_t smem_u32(const void* p) {
    uint32_t a;
    asm("{ .reg .u64 t; cvta.to.shared.u64 t, %1; cvt.u32.u64 %0, t; }" : "=r"(a) : "l"(p));
    return a;
}
__device__ __forceinline__ void cp_async16(uint32_t dst, const void* src) {
    asm volatile("cp.async.cg.shared.global [%0], [%1], 16;" :: "r"(dst), "l"(src) : "memory");
}
__device__ __forceinline__ void sts_fill16(uint32_t dst, uint32_t v) {
    asm volatile("st.shared.v4.b32 [%0], {%1, %1, %1, %1};" :: "r"(dst), "r"(v) : "memory");
}
__device__ __forceinline__ void cp_commit() {
    asm volatile("cp.async.commit_group;" ::: "memory");
}
template <int N>
__device__ __forceinline__ void cp_wait() {
    asm volatile("cp.async.wait_group %0;" :: "n"(N) : "memory");
}
__device__ __forceinline__ void ldsm_x4(uint32_t* r, uint32_t addr) {
    asm volatile("ldmatrix.sync.aligned.m8n8.x4.shared.b16 {%0,%1,%2,%3}, [%4];"
                 : "=r"(r[0]), "=r"(r[1]), "=r"(r[2]), "=r"(r[3]) : "r"(addr));
}
__device__ __forceinline__ void mma16816(float* d, const uint32_t* a, const uint32_t* b) {
    asm volatile(
        "mma.sync.aligned.m16n8k16.row.col.f32.f16.f16.f32 "
        "{%0,%1,%2,%3}, {%4,%5,%6,%7}, {%8,%9}, {%0,%1,%2,%3};"
        : "+f"(d[0]), "+f"(d[1]), "+f"(d[2]), "+f"(d[3])
        : "r"(a[0]), "r"(a[1]), "r"(a[2]), "r"(a[3]), "r"(b[0]), "r"(b[1]));
}

// ============================================================
// Kernel 1a: features fp32 -> fp16
// ============================================================
__global__ void cvt_features_kernel(const float* __restrict__ f) {
    size_t idx = (size_t)blockIdx.x * blockDim.x + threadIdx.x;
    if (idx >= (size_t)N_ACT * CDIM / 4) return;
    float4 v = reinterpret_cast<const float4*>(f)[idx];
    __half2* dst = reinterpret_cast<__half2*>(g_Af16) + 2 * idx;
    dst[0] = __floats2half2_rn(v.x, v.y);
    dst[1] = __floats2half2_rn(v.z, v.w);
}

// ============================================================
// Kernel 1b: W [k][cin][cout] fp32 -> Wt [k][cout][cin] fp16
// ============================================================
__global__ void cvt_w_kernel(const float* __restrict__ W) {
    int m = blockIdx.x * blockDim.x + threadIdx.x;
    int k   = m >> 14;
    int rem = m & 16383;
    int c   = rem >> 7;   // cout
    int j   = rem & 127;  // cin
    g_Wt16[m] = __float2half_rn(W[(k << 14) + (j << 7) + c]);
}

// ============================================================
// Kernel 2: compacted sparse conv via mma.sync (HMMA fp16 -> fp32)
// ============================================================
__global__ void __launch_bounds__(CONV_THREADS, 1)
conv_kernel(const int* __restrict__ nbr, float* __restrict__ out) {
    extern __shared__ char smem[];
    const uint32_t sb = smem_u32(smem);
    const int tid = threadIdx.x;
    const int wid = tid >> 5;
    const int lid = tid & 31;
    const int wm  = wid & 3;    // accum M group (64 rows)
    const int wn  = wid >> 2;   // accum N group (32 cols)
    const int row0 = blockIdx.x * BM;

    int*     s_cidx = reinterpret_cast<int*>(smem + OFF_CIDX);
    int16_t* s_pos  = reinterpret_cast<int16_t*>(smem + OFF_POS);
    int*     s_cnt  = reinterpret_cast<int*>(smem + OFF_CNT);
    int*     s_wtot = reinterpret_cast<int*>(smem + OFF_WTOT);
    int*     s_work = reinterpret_cast<int*>(smem + OFF_WORK);
    int*     s_nw   = reinterpret_cast<int*>(smem + OFF_NW);
    float*   stg    = reinterpret_cast<float*>(smem + OFF_STG);

    // ---- prefetch this CTA's nbr block (27 x 256 int32) into s_cidx ----
    for (int c = tid; c < KOFF * 64; c += CONV_THREADS) {   // 16B chunks (4 ints)
        int k   = c >> 6;
        int off = (c & 63) * 16;                            // byte offset in 256-row seg
        int rL  = row0 + (off >> 2) + 3;
        uint32_t dst = sb + OFF_CIDX + (uint32_t)c * 16u;
        if (rL < N_ACT)
            cp_async16(dst, (const char*)(nbr + (size_t)k * N_ACT + row0) + off);
        else
            sts_fill16(dst, 0xFFFFFFFFu);
    }
    cp_commit();
    cp_wait<0>();
    __syncthreads();

    // ---- per-offset compaction: valid lists + row->pos table ----
    for (int k = 0; k < KOFF; k++) {
        int idx = -1;
        bool valid = false;
        if (tid < BM) {
            idx = s_cidx[k * 256 + tid];
            valid = (idx >= 0);
        }
        unsigned bal = __ballot_sync(0xFFFFFFFFu, valid);
        if (tid < BM && lid == 0) s_wtot[wid] = __popc(bal);
        __syncthreads();
        if (tid < BM) {
            int base = 0;
            #pragma unroll
            for (int w = 0; w < 8; w++) base += (w < wid) ? s_wtot[w] : 0;
            int pre = __popc(bal & ((1u << lid) - 1u));
            int pos = base + pre;
            s_pos[k * 256 + tid] = valid ? (int16_t)pos : (int16_t)-1;
            if (valid) s_cidx[k * 256 + pos] = idx;   // safe: pos <= tid, reads done
            if (tid == 0) {
                int tot = 0;
                #pragma unroll
                for (int w = 0; w < 8; w++) tot += s_wtot[w];
                s_cnt[k] = tot;
            }
        }
        __syncthreads();
    }

    // ---- build flattened (k, subtile) work list ----
    if (tid == 0) {
        int nw = 0;
        for (int k = 0; k < KOFF; k++) {
            int ns = (s_cnt[k] + 63) >> 6;
            for (int s = 0; s < ns; s++) s_work[nw++] = (k << 4) | s;
        }
        *s_nw = nw;
    }
    __syncthreads();
    const int nwork = *s_nw;

    // ---- accumulators (row r = row0 + wm*64 + mf*16 + (lid>>2) + h*8,
    //      col c = wn*32 + nf*8 + (lid&3)*2) ----
    float acc[4][4][4];
    #pragma unroll
    for (int a = 0; a < 4; a++)
        #pragma unroll
        for (int b = 0; b < 4; b++)
            #pragma unroll
            for (int c = 0; c < 4; c++) acc[a][b][c] = 0.f;

    // ---- tile loaders ----
    auto load_A = [&](int w, int buf) {
        int e = s_work[w];
        int k = e >> 4, s = e & 15;
        int cnt = s_cnt[k];
        int p = tid >> 3;          // compact row slot 0..63
        int o = tid & 7;           // 16B chunk (and +8)
        uint32_t dst = sb + OFF_A + (uint32_t)buf * A_TILE + (uint32_t)p * ROWB + (uint32_t)o * 16u;
        int pos = s * 64 + p;
        if (pos < cnt) {
            const char* src = (const char*)g_Af16 + (size_t)s_cidx[k * 256 + pos] * 256 + o * 16;
            cp_async16(dst, src);
            cp_async16(dst + 128u, src + 128);
        } else {
            sts_fill16(dst, 0u);
            sts_fill16(dst + 128u, 0u);
        }
    };
    auto load_B = [&](int k, int buf) {
        int n = tid >> 2;
        int q = tid & 3;
        uint32_t dst = sb + OFF_B + (uint32_t)buf * B_TILE + (uint32_t)n * ROWB + (uint32_t)q * 64u;
        const char* src = (const char*)g_Wt16 + ((size_t)k * 128 + n) * 256 + (size_t)q * 64;
        #pragma unroll
        for (int c = 0; c < 4; c++)
            cp_async16(dst + c * 16u, src + c * 16);
    };

    // ---- per-lane ldmatrix address pieces (subtile GEMM: 2M x 8N warps) ----
    const uint32_t a_row2  = (uint32_t)((wid & 1) * 32 + (lid & 15));
    const uint32_t a_coff  = (uint32_t)(lid >> 4) * 16u;
    const uint32_t b_row2  = (uint32_t)((wid >> 1) * 16 + (lid & 7) + ((lid & 16) ? 8 : 0));
    const uint32_t b_coff  = (uint32_t)((lid >> 3) & 1) * 16u;
    const int srow0 = (wid & 1) * 32 + (lid >> 2);
    const int scol0 = (wid >> 1) * 16 + (lid & 3) * 2;
    const int r_base = wm * 64 + (lid >> 2);
    const int c_base = wn * 32 + (lid & 3) * 2;

    // ---- prime pipeline ----
    load_A(0, 0);
    load_B(s_work[0] >> 4, 0);
    cp_commit();
    int abuf = 0, bbuf = 0;

    #pragma unroll 1
    for (int w = 0; w < nwork; w++) {
        const int e = s_work[w];
        const int k = e >> 4, s = e & 15;
        const int knext = (w + 1 < nwork) ? (s_work[w + 1] >> 4) : -1;
        const bool newb = (knext >= 0 && knext != k);
        if (w + 1 < nwork) {
            load_A(w + 1, abuf ^ 1);
            if (newb) load_B(knext, bbuf ^ 1);
            cp_commit();
            cp_wait<1>();
        } else {
            cp_wait<0>();
        }
        __syncthreads();

        // ---- 64x128x128 compact GEMM ----
        float facc[2][2][4];
        #pragma unroll
        for (int a = 0; a < 2; a++)
            #pragma unroll
            for (int b = 0; b < 2; b++)
                #pragma unroll
                for (int c = 0; c < 4; c++) facc[a][b][c] = 0.f;
        {
            const uint32_t ab = sb + OFF_A + (uint32_t)abuf * A_TILE;
            const uint32_t bb = sb + OFF_B + (uint32_t)bbuf * B_TILE;
            #pragma unroll
            for (int ks = 0; ks < 8; ks++) {
                uint32_t af0[4], af1[4], t[4];
                ldsm_x4(af0, ab + a_row2 * ROWB + (uint32_t)ks * 32u + a_coff);
                ldsm_x4(af1, ab + (a_row2 + 16u) * ROWB + (uint32_t)ks * 32u + a_coff);
                ldsm_x4(t,   bb + b_row2 * ROWB + (uint32_t)ks * 32u + b_coff);
                uint32_t bf0[2] = {t[0], t[1]};
                uint32_t bf1[2] = {t[2], t[3]};
                mma16816(facc[0][0], af0, bf0);
                mma16816(facc[0][1], af0, bf1);
                mma16816(facc[1][0], af1, bf0);
                mma16816(facc[1][1], af1, bf1);
            }
        }
        // ---- stage compact result to smem ----
        #pragma unroll
        for (int mf = 0; mf < 2; mf++)
            #pragma unroll
            for (int h = 0; h < 2; h++) {
                int rr = srow0 + mf * 16 + h * 8;
                #pragma unroll
                for (int nf = 0; nf < 2; nf++) {
                    float2 v = make_float2(facc[mf][nf][2 * h], facc[mf][nf][2 * h + 1]);
                    *reinterpret_cast<float2*>(&stg[rr * STG_STRIDE + scol0 + nf * 8]) = v;
                }
            }
        __syncthreads();

        // ---- scatter-add into persistent accumulators ----
        {
            const int16_t* posk = s_pos + k * 256;
            const int base_s = s * 64;
            #pragma unroll
            for (int mf = 0; mf < 4; mf++)
                #pragma unroll
                for (int h = 0; h < 2; h++) {
                    int r = r_base + mf * 16 + h * 8;
                    int p = posk[r];
                    if (p >= base_s && p < base_s + 64) {
                        int srow = p - base_s;
                        #pragma unroll
                        for (int nf = 0; nf < 4; nf++) {
                            float2 v = *reinterpret_cast<const float2*>(
                                &stg[srow * STG_STRIDE + c_base + nf * 8]);
                            acc[mf][nf][2 * h]     += v.x;
                            acc[mf][nf][2 * h + 1] += v.y;
                        }
                    }
                }
        }
        __syncthreads();

        abuf ^= 1;
        if (newb) bbuf ^= 1;
    }

    // ---- epilogue: store conv output (pre-BN) ----
    {
        #pragma unroll
        for (int mf = 0; mf < 4; mf++)
            #pragma unroll
            for (int h = 0; h < 2; h++) {
                int r = row0 + r_base + mf * 16 + h * 8;
                if (r < N_ACT) {
                    float* dst = out + (size_t)r * CDIM + c_base;
                    #pragma unroll
                    for (int nf = 0; nf < 4; nf++) {
                        float2 v = make_float2(acc[mf][nf][2 * h], acc[mf][nf][2 * h + 1]);
                        *reinterpret_cast<float2*>(dst + nf * 8) = v;
                    }
                }
            }
    }

    // ---- fused BN partials (deterministic, no atomics) ----
    {
        float s[8], q[8];
        #pragma unroll
        for (int nf = 0; nf < 4; nf++)
            #pragma unroll
            for (int jj = 0; jj < 2; jj++) {
                float ss = 0.f, qq = 0.f;
                #pragma unroll
                for (int mf = 0; mf < 4; mf++) {
                    float v0 = acc[mf][nf][jj];
                    float v1 = acc[mf][nf][jj + 2];
                    ss += v0 + v1;
                    qq = fmaf(v0, v0, qq);
                    qq = fmaf(v1, v1, qq);
                }
                s[nf * 2 + jj] = ss;
                q[nf * 2 + jj] = qq;
            }
        #pragma unroll
        for (int st = 4; st <= 16; st <<= 1)
            #pragma unroll
            for (int j = 0; j < 8; j++) {
                s[j] += __shfl_xor_sync(0xFFFFFFFFu, s[j], st);
                q[j] += __shfl_xor_sync(0xFFFFFFFFu, q[j], st);
            }
        __syncthreads();
        float* red = reinterpret_cast<float*>(smem);   // reuse tiles
        if (lid < 4) {
            #pragma unroll
            for (int nf = 0; nf < 4; nf++)
                #pragma unroll
                for (int jj = 0; jj < 2; jj++) {
                    int ch = wn * 32 + nf * 8 + lid * 2 + jj;
                    red[wm * 128 + ch]       = s[nf * 2 + jj];
                    red[512 + wm * 128 + ch] = q[nf * 2 + jj];
                }
        }
        __syncthreads();
        if (tid < CDIM) {
            float ts = 0.f, tq = 0.f;
            #pragma unroll
            for (int ww = 0; ww < 4; ww++) {
                ts += red[ww * 128 + tid];
                tq += red[512 + ww * 128 + tid];
            }
            g_psum[blockIdx.x * CDIM + tid] = ts;
            g_psq [blockIdx.x * CDIM + tid] = tq;
        }
    }
}

// ============================================================
// Kernel 3: finalize BN scale/bias (parallel, deterministic tree)
// ============================================================
__global__ void bn_final_kernel(const float* __restrict__ gamma, const float* __restrict__ beta) {
    __shared__ float ss[256], sq[256];
    int c = blockIdx.x;
    int t = threadIdx.x;
    float s = 0.f, q = 0.f;
    for (int b = t; b < NBLK; b += 256) {
        s += g_psum[b * CDIM + c];
        q += g_psq [b * CDIM + c];
    }
    ss[t] = s; sq[t] = q;
    __syncthreads();
    #pragma unroll
    for (int st = 128; st > 0; st >>= 1) {
        if (t < st) { ss[t] += ss[t + st]; sq[t] += sq[t + st]; }
        __syncthreads();
    }
    if (t == 0) {
        float mean = ss[0] / (float)N_ACT;
        float var  = sq[0] / (float)N_ACT - mean * mean;
        float sc   = gamma[c] * rsqrtf(var + BN_EPS);
        g_scale[c] = sc;
        g_bias[c]  = beta[c] - mean * sc;
    }
}

// ============================================================
// Kernel 4: apply BN + ReLU elementwise
// ============================================================
__global__ void bn_apply_kernel(float* __restrict__ out) {
    size_t idx = (size_t)blockIdx.x * blockDim.x + threadIdx.x;
    if (idx >= (size_t)N_ACT * CDIM / 4) return;
    int c4 = (int)(idx & 31);
    float4 v  = reinterpret_cast<float4*>(out)[idx];
    float4 sc = reinterpret_cast<float4*>(g_scale)[c4];
    float4 bi = reinterpret_cast<float4*>(g_bias)[c4];
    v.x = fmaxf(fmaf(v.x, sc.x, bi.x), 0.f);
    v.y = fmaxf(fmaf(v.y, sc.y, bi.y), 0.f);
    v.z = fmaxf(fmaf(v.z, sc.z, bi.z), 0.f);
    v.w = fmaxf(fmaf(v.w, sc.w, bi.w), 0.f);
    reinterpret_cast<float4*>(out)[idx] = v;
}

// ============================================================
// Launch
// ============================================================
extern "C" void kernel_launch(void* const* d_in, const int* in_sizes, int n_in,
                              void* d_out, int out_size) {
    const float* features = (const float*)d_in[0];
    const int*   nbr      = (const int*)d_in[1];
    const float* W        = (const float*)d_in[2];
    const float* gamma    = (const float*)d_in[3];
    const float* beta     = (const float*)d_in[4];
    float* out = (float*)d_out;

    cudaFuncSetAttribute((const void*)conv_kernel,
                         cudaFuncAttributeMaxDynamicSharedMemorySize, SMEM_TOTAL);

    const int chunks = N_ACT * CDIM / 4;
    cvt_features_kernel<<<(chunks + 255) / 256, 256>>>(features);
    cvt_w_kernel<<<KOFF * CDIM * CDIM / 256, 256>>>(W);
    conv_kernel<<<NBLK, CONV_THREADS, SMEM_TOTAL>>>(nbr, out);
    bn_final_kernel<<<CDIM, 256>>>(gamma, beta);
    bn_apply_kernel<<<(chunks + 255) / 256, 256>>>(out);
}

// round 4
// speedup vs baseline: 1.3341x; 1.0481x over previous
#include <cuda_runtime.h>
#include <cuda_fp16.h>
#include <cstdint>
#include <cstddef>

// ============================================================
// Problem constants
// ============================================================
constexpr int N_ACT = 200000;
constexpr int CDIM  = 128;
constexpr int KOFF  = 27;
constexpr float BN_EPS = 1e-4f;

constexpr int BM           = 256;                       // output rows per CTA
constexpr int NBLK         = (N_ACT + BM - 1) / BM;     // 782
constexpr int CONV_THREADS = 512;                       // 16 warps

// SMEM layout (dynamic)
constexpr uint32_t ROWB     = 272;                      // fp16 tile row stride (conflict-free ldmatrix)
constexpr uint32_t OFF_ACC  = 0;                        // 256 x 128 fp32, XOR-swizzled pairs
constexpr uint32_t ACC_B    = 256u * 512u;              // 131072
constexpr uint32_t OFF_A    = OFF_ACC + ACC_B;          // 131072 ; 2 x 64x272
constexpr uint32_t A_TILE   = 64u * ROWB;               // 17408
constexpr uint32_t OFF_B    = OFF_A + 2u * A_TILE;      // 165888 ; 128x272 single buffer
constexpr uint32_t B_TILE   = 128u * ROWB;              // 34816
constexpr uint32_t OFF_CIDX = OFF_B + B_TILE;           // 200704 ; 27*256 packed (idx | row<<18)
constexpr uint32_t OFF_CNT  = OFF_CIDX + 27648;         // 228352 ; 27 ints (pad 128)
constexpr uint32_t OFF_WTOT = OFF_CNT + 128;            // 228480 ; 8 ints
constexpr uint32_t OFF_WORK = OFF_WTOT + 32;            // 228512 ; 112 ints
constexpr uint32_t OFF_NW   = OFF_WORK + 448;           // 228960
constexpr uint32_t SMEM_TOTAL = OFF_NW + 32;            // 228992  (< 232448 limit)

// ============================================================
// Device scratch
// ============================================================
__device__ __align__(16) __half g_Af16[(size_t)N_ACT * CDIM];          // 51.2 MB
__device__ __align__(16) __half g_Wt16[(size_t)KOFF * CDIM * CDIM];    // [k][cout][cin]
__device__ float g_psum[NBLK * CDIM];
__device__ float g_psq [NBLK * CDIM];
__device__ __align__(16) float g_scale[CDIM];
__device__ __align__(16) float g_bias [CDIM];

// ============================================================
// Helpers
// ============================================================
__device__ __forceinline__ uint32_t smem_u32(const void* p) {
    uint32_t a;
    asm("{ .reg .u64 t; cvta.to.shared.u64 t, %1; cvt.u32.u64 %0, t; }" : "=r"(a) : "l"(p));
    return a;
}
__device__ __forceinline__ void cp_async16(uint32_t dst, const void* src) {
    asm volatile("cp.async.cg.shared.global [%0], [%1], 16;" :: "r"(dst), "l"(src) : "memory");
}
__device__ __forceinline__ void sts_fill16(uint32_t dst, uint32_t v) {
    asm volatile("st.shared.v4.b32 [%0], {%1, %1, %1, %1};" :: "r"(dst), "r"(v) : "memory");
}
__device__ __forceinline__ void cp_commit() {
    asm volatile("cp.async.commit_group;" ::: "memory");
}
template <int N>
__device__ __forceinline__ void cp_wait() {
    asm volatile("cp.async.wait_group %0;" :: "n"(N) : "memory");
}
__device__ __forceinline__ void ldsm_x4(uint32_t* r, uint32_t addr) {
    asm volatile("ldmatrix.sync.aligned.m8n8.x4.shared.b16 {%0,%1,%2,%3}, [%4];"
                 : "=r"(r[0]), "=r"(r[1]), "=r"(r[2]), "=r"(r[3]) : "r"(addr));
}
__device__ __forceinline__ void mma16816(float* d, const uint32_t* a, const uint32_t* b) {
    asm volatile(
        "mma.sync.aligned.m16n8k16.row.col.f32.f16.f16.f32 "
        "{%0,%1,%2,%3}, {%4,%5,%6,%7}, {%8,%9}, {%0,%1,%2,%3};"
        : "+f"(d[0]), "+f"(d[1]), "+f"(d[2]), "+f"(d[3])
        : "r"(a[0]), "r"(a[1]), "r"(a[2]), "r"(a[3]), "r"(b[0]), "r"(b[1]));
}

// Accumulator address: pair index pp (0..63), row r (0..255).
// Row stride 512B; pair swizzled by (r & 7) to spread banks.
__device__ __forceinline__ uint32_t acc_addr(uint32_t sb, int r, int pp) {
    return sb + OFF_ACC + (uint32_t)r * 512u + (uint32_t)((pp ^ (r & 7)) << 3);
}

// ============================================================
// Kernel 1a: features fp32 -> fp16
// ============================================================
__global__ void cvt_features_kernel(const float* __restrict__ f) {
    size_t idx = (size_t)blockIdx.x * blockDim.x + threadIdx.x;
    if (idx >= (size_t)N_ACT * CDIM / 4) return;
    float4 v = reinterpret_cast<const float4*>(f)[idx];
    __half2* dst = reinterpret_cast<__half2*>(g_Af16) + 2 * idx;
    dst[0] = __floats2half2_rn(v.x, v.y);
    dst[1] = __floats2half2_rn(v.z, v.w);
}

// ============================================================
// Kernel 1b: W [k][cin][cout] fp32 -> Wt [k][cout][cin] fp16
// ============================================================
__global__ void cvt_w_kernel(const float* __restrict__ W) {
    int m = blockIdx.x * blockDim.x + threadIdx.x;
    int k   = m >> 14;
    int rem = m & 16383;
    int c   = rem >> 7;   // cout
    int j   = rem & 127;  // cin
    g_Wt16[m] = __float2half_rn(W[(k << 14) + (j << 7) + c]);
}

// ============================================================
// Dummy kernel (slot-shifter so ncu captures conv_kernel)
// ============================================================
__global__ void dummy_kernel() {}

// ============================================================
// Kernel 2: compacted sparse conv, SMEM-resident fp32 accumulator
// ============================================================
__global__ void __launch_bounds__(CONV_THREADS, 1)
conv_kernel(const int* __restrict__ nbr, float* __restrict__ out) {
    extern __shared__ char smem[];
    const uint32_t sb = smem_u32(smem);
    const int tid = threadIdx.x;
    const int wid = tid >> 5;
    const int lid = tid & 31;
    const int row0 = blockIdx.x * BM;

    int* s_cidx = reinterpret_cast<int*>(smem + OFF_CIDX);
    int* s_cnt  = reinterpret_cast<int*>(smem + OFF_CNT);
    int* s_wtot = reinterpret_cast<int*>(smem + OFF_WTOT);
    int* s_work = reinterpret_cast<int*>(smem + OFF_WORK);
    int* s_nw   = reinterpret_cast<int*>(smem + OFF_NW);

    // ---- zero the smem accumulator (32768 floats) ----
    {
        float4* a4 = reinterpret_cast<float4*>(smem + OFF_ACC);
        #pragma unroll
        for (int i = 0; i < 16; i++)
            a4[tid + i * CONV_THREADS] = make_float4(0.f, 0.f, 0.f, 0.f);
    }

    // ---- prefetch this CTA's nbr block (27 x 256 int32) ----
    for (int c = tid; c < KOFF * 64; c += CONV_THREADS) {   // 16B chunks (4 rows each)
        int k   = c >> 6;
        int off = (c & 63) * 16;
        int rL  = row0 + (off >> 2) + 3;
        uint32_t dst = sb + OFF_CIDX + (uint32_t)c * 16u;
        if (rL < N_ACT)
            cp_async16(dst, (const char*)(nbr + (size_t)k * N_ACT + row0) + off);
        else
            sts_fill16(dst, 0xFFFFFFFFu);
    }
    cp_commit();
    cp_wait<0>();
    __syncthreads();

    // ---- per-offset compaction: pack (idx | local_row<<18) lists ----
    for (int k = 0; k < KOFF; k++) {
        int idx = -1;
        bool valid = false;
        if (tid < BM) {
            idx = s_cidx[k * 256 + tid];
            valid = (idx >= 0);
        }
        unsigned bal = __ballot_sync(0xFFFFFFFFu, valid);
        if (tid < BM && lid == 0) s_wtot[wid] = __popc(bal);
        __syncthreads();   // all reads done; wtot visible
        if (tid < BM) {
            int base = 0;
            #pragma unroll
            for (int w = 0; w < 8; w++) base += (w < wid) ? s_wtot[w] : 0;
            int pos = base + __popc(bal & ((1u << lid) - 1u));
            if (valid) s_cidx[k * 256 + pos] = idx | (tid << 18);
            if (tid == 0) {
                int tot = 0;
                #pragma unroll
                for (int w = 0; w < 8; w++) tot += s_wtot[w];
                s_cnt[k] = tot;
            }
        }
        __syncthreads();
    }

    // ---- build (k, subtile) work list ----
    if (tid == 0) {
        int nw = 0;
        for (int k = 0; k < KOFF; k++) {
            int ns = (s_cnt[k] + 63) >> 6;
            for (int s = 0; s < ns; s++) s_work[nw++] = (k << 4) | s;
        }
        *s_nw = nw;
    }
    __syncthreads();
    const int nwork = *s_nw;

    // ---- tile loaders ----
    auto load_A = [&](int w, int buf) {
        int e = s_work[w];
        int k = e >> 4, s = e & 15;
        int cnt = s_cnt[k];
        int p = tid >> 3;          // compact slot 0..63
        int o = tid & 7;           // 16B chunk
        uint32_t dst = sb + OFF_A + (uint32_t)buf * A_TILE + (uint32_t)p * ROWB + (uint32_t)o * 16u;
        int pos = s * 64 + p;
        if (pos < cnt) {
            uint32_t ent = (uint32_t)s_cidx[k * 256 + pos];
            const char* src = (const char*)g_Af16 + (size_t)(ent & 0x3FFFFu) * 256 + o * 16;
            cp_async16(dst, src);
            cp_async16(dst + 128u, src + 128);
        } else {
            sts_fill16(dst, 0u);
            sts_fill16(dst + 128u, 0u);
        }
    };
    auto load_B = [&](int k) {
        int n = tid >> 2;
        int q = tid & 3;
        uint32_t dst = sb + OFF_B + (uint32_t)n * ROWB + (uint32_t)q * 64u;
        const char* src = (const char*)g_Wt16 + ((size_t)k * 128 + n) * 256 + (size_t)q * 64;
        #pragma unroll
        for (int c = 0; c < 4; c++)
            cp_async16(dst + c * 16u, src + c * 16);
    };

    // ---- per-lane fragment address pieces (16 warps: 2M x 8N over 64x128) ----
    const uint32_t a_row2 = (uint32_t)((wid & 1) * 32 + (lid & 15));
    const uint32_t a_coff = (uint32_t)(lid >> 4) * 16u;
    const uint32_t b_row2 = (uint32_t)((wid >> 1) * 16 + (lid & 7) + ((lid & 16) ? 8 : 0));
    const uint32_t b_coff = (uint32_t)((lid >> 3) & 1) * 16u;
    const int p_base  = (wid & 1) * 32 + (lid >> 2);        // compact row base
    const int pp_base = (wid >> 1) * 8 + (lid & 3);         // pair-index base

    // ---- prime pipeline: group0 = {B(k0), A(unit0)} ----
    load_B(s_work[0] >> 4);
    load_A(0, 0);
    cp_commit();
    int abuf = 0;

    #pragma unroll 1
    for (int w = 0; w < nwork; w++) {
        const int e = s_work[w];
        const int k = e >> 4, s = e & 15;
        const int cnt = s_cnt[k];
        const int knext = (w + 1 < nwork) ? (s_work[w + 1] >> 4) : -1;

        if (w + 1 < nwork) {
            load_A(w + 1, abuf ^ 1);
            cp_commit();
            cp_wait<1>();
        } else {
            cp_wait<0>();
        }
        __syncthreads();   // S1: tiles visible; prior scatter complete

        // ---- 64x128x128 compact GEMM ----
        float facc[2][2][4];
        #pragma unroll
        for (int a = 0; a < 2; a++)
            #pragma unroll
            for (int b = 0; b < 2; b++)
                #pragma unroll
                for (int c = 0; c < 4; c++) facc[a][b][c] = 0.f;
        {
            const uint32_t ab = sb + OFF_A + (uint32_t)abuf * A_TILE;
            const uint32_t bb = sb + OFF_B;
            #pragma unroll
            for (int ks = 0; ks < 8; ks++) {
                uint32_t af0[4], af1[4], t[4];
                ldsm_x4(af0, ab + a_row2 * ROWB + (uint32_t)ks * 32u + a_coff);
                ldsm_x4(af1, ab + (a_row2 + 16u) * ROWB + (uint32_t)ks * 32u + a_coff);
                ldsm_x4(t,   bb + b_row2 * ROWB + (uint32_t)ks * 32u + b_coff);
                uint32_t bf0[2] = {t[0], t[1]};
                uint32_t bf1[2] = {t[2], t[3]};
                mma16816(facc[0][0], af0, bf0);
                mma16816(facc[0][1], af0, bf1);
                mma16816(facc[1][0], af1, bf0);
                mma16816(facc[1][1], af1, bf1);
            }
        }
        __syncthreads();   // S2: all warps done reading A(w) and B(k)

        if (knext >= 0 && knext != k) {   // B buffer now free
            load_B(knext);
            cp_commit();
        }

        // ---- direct scatter-add into smem accumulator ----
        {
            const int base_s = s * 64;
            #pragma unroll
            for (int mf = 0; mf < 2; mf++)
                #pragma unroll
                for (int h = 0; h < 2; h++) {
                    int p = p_base + mf * 16 + h * 8;
                    int pos = base_s + p;
                    if (pos < cnt) {
                        int r = ((uint32_t)s_cidx[k * 256 + pos]) >> 18;
                        #pragma unroll
                        for (int nf = 0; nf < 2; nf++) {
                            uint32_t ad = acc_addr(sb, r, pp_base + nf * 4);
                            float2 v = *reinterpret_cast<float2*>(smem + (ad - sb));
                            v.x += facc[mf][nf][2 * h];
                            v.y += facc[mf][nf][2 * h + 1];
                            *reinterpret_cast<float2*>(smem + (ad - sb)) = v;
                        }
                    }
                }
        }
        abuf ^= 1;
    }
    __syncthreads();   // final scatter complete

    // ---- epilogue: smem acc -> out, + BN partials ----
    {
        const int pp = tid & 63;     // pair (2 channels)
        const int g  = tid >> 6;     // row group 0..7 (32 rows each)
        float s0 = 0.f, s1 = 0.f, q0 = 0.f, q1 = 0.f;
        #pragma unroll 4
        for (int rr = 0; rr < 32; rr++) {
            int r = g * 32 + rr;
            float2 v = *reinterpret_cast<float2*>(smem + (acc_addr(sb, r, pp) - sb));
            int row = row0 + r;
            if (row < N_ACT)
                *reinterpret_cast<float2*>(out + (size_t)row * CDIM + pp * 2) = v;
            s0 += v.x; s1 += v.y;
            q0 = fmaf(v.x, v.x, q0);
            q1 = fmaf(v.y, v.y, q1);
        }
        __syncthreads();
        float4* red = reinterpret_cast<float4*>(smem + OFF_A);   // [8][64]
        red[g * 64 + pp] = make_float4(s0, s1, q0, q1);
        __syncthreads();
        if (tid < 64) {
            float ts0 = 0.f, ts1 = 0.f, tq0 = 0.f, tq1 = 0.f;
            #pragma unroll
            for (int gg = 0; gg < 8; gg++) {
                float4 v = red[gg * 64 + tid];
                ts0 += v.x; ts1 += v.y; tq0 += v.z; tq1 += v.w;
            }
            g_psum[blockIdx.x * CDIM + tid * 2]     = ts0;
            g_psum[blockIdx.x * CDIM + tid * 2 + 1] = ts1;
            g_psq [blockIdx.x * CDIM + tid * 2]     = tq0;
            g_psq [blockIdx.x * CDIM + tid * 2 + 1] = tq1;
        }
    }
}

// ============================================================
// Kernel 3: finalize BN scale/bias (parallel, deterministic tree)
// ============================================================
__global__ void bn_final_kernel(const float* __restrict__ gamma, const float* __restrict__ beta) {
    __shared__ float ss[256], sq[256];
    int c = blockIdx.x;
    int t = threadIdx.x;
    float s = 0.f, q = 0.f;
    for (int b = t; b < NBLK; b += 256) {
        s += g_psum[b * CDIM + c];
        q += g_psq [b * CDIM + c];
    }
    ss[t] = s; sq[t] = q;
    __syncthreads();
    #pragma unroll
    for (int st = 128; st > 0; st >>= 1) {
        if (t < st) { ss[t] += ss[t + st]; sq[t] += sq[t + st]; }
        __syncthreads();
    }
    if (t == 0) {
        float mean = ss[0] / (float)N_ACT;
        float var  = sq[0] / (float)N_ACT - mean * mean;
        float sc   = gamma[c] * rsqrtf(var + BN_EPS);
        g_scale[c] = sc;
        g_bias[c]  = beta[c] - mean * sc;
    }
}

// ============================================================
// Kernel 4: apply BN + ReLU elementwise
// ============================================================
__global__ void bn_apply_kernel(float* __restrict__ out) {
    size_t idx = (size_t)blockIdx.x * blockDim.x + threadIdx.x;
    if (idx >= (size_t)N_ACT * CDIM / 4) return;
    int c4 = (int)(idx & 31);
    float4 v  = reinterpret_cast<float4*>(out)[idx];
    float4 sc = reinterpret_cast<float4*>(g_scale)[c4];
    float4 bi = reinterpret_cast<float4*>(g_bias)[c4];
    v.x = fmaxf(fmaf(v.x, sc.x, bi.x), 0.f);
    v.y = fmaxf(fmaf(v.y, sc.y, bi.y), 0.f);
    v.z = fmaxf(fmaf(v.z, sc.z, bi.z), 0.f);
    v.w = fmaxf(fmaf(v.w, sc.w, bi.w), 0.f);
    reinterpret_cast<float4*>(out)[idx] = v;
}

// ============================================================
// Launch
// ============================================================
extern "C" void kernel_launch(void* const* d_in, const int* in_sizes, int n_in,
                              void* d_out, int out_size) {
    const float* features = (const float*)d_in[0];
    const int*   nbr      = (const int*)d_in[1];
    const float* W        = (const float*)d_in[2];
    const float* gamma    = (const float*)d_in[3];
    const float* beta     = (const float*)d_in[4];
    float* out = (float*)d_out;

    cudaFuncSetAttribute((const void*)conv_kernel,
                         cudaFuncAttributeMaxDynamicSharedMemorySize, SMEM_TOTAL);

    const int chunks = N_ACT * CDIM / 4;
    cvt_features_kernel<<<(chunks + 255) / 256, 256>>>(features);
    cvt_w_kernel<<<KOFF * CDIM * CDIM / 256, 256>>>(W);
    dummy_kernel<<<1, 32>>>();   // shifts conv into ncu's capture slot
    conv_kernel<<<NBLK, CONV_THREADS, SMEM_TOTAL>>>(nbr, out);
    bn_final_kernel<<<CDIM, 256>>>(gamma, beta);
    bn_apply_kernel<<<(chunks + 255) / 256, 256>>>(out);
}